// round 16
// baseline (speedup 1.0000x reference)
#include <cuda_runtime.h>
#include <cuda_bf16.h>
#include <mma.h>
#include <cstdint>

using namespace nvcuda;

// Problem constants
#define Bq 32
#define Sq 2048
#define Dq 512
#define Hq 32
#define NTOK (Bq * Sq)        // 65536
#define GRID 152
#define NT   512              // 16 warps = 8 independent streams of 2

// ---------------- shared layout (float offsets) ----------------
// Per stream: FB = 4128 floats. fp32 rows 0-7 at [0, 2048*8B); bf16 image
// (8 rows x XB_STRIDE) in place at byte offset 8192, extent ends 16512 B.
#define XB_STRIDE 520             // bf16 row stride (1040 B)
#define WS_STRIDE 40
#define SM_HT   0                 // Ht swizzled 32x32             -> 1024
#define SM_TBL  1024              // ints P[33]+scnt[32], pad      -> 1104
#define SM_SW   1104              // per-stream ints [8], pad      -> 1120
#define SM_WS   1120              // Ws[8][8][40]                  -> 3680
#define SM_FB   3680              // FB [8][4128]                  -> 36704
#define SM_PB   36704             // P bf16 [32][520] (8320 f)     -> 45024
#define SM_FLOATS 45024
#define SMEM_BYTES (SM_FLOATS * 4)   // 180096

#define RSCALE 0.17677669529663687f  // 1/sqrt(32)

// ---------------- scratch ----------------
__device__ int      g_bcnt[256];
__device__ int      g_cnt[Bq];
__device__ int      g_idx[NTOK];
__device__ float    g_bsum[Bq];
__device__ float    g_acc[Bq * Dq];
__device__ unsigned g_bar1 = 0u;
__device__ unsigned g_bar2 = 0u;
__device__ unsigned g_work = 0u;     // dynamic slice counter (reset by k_prep)

// ---------------- helpers ----------------
__device__ __forceinline__ void fma2(unsigned long long& d,
                                     unsigned long long a,
                                     unsigned long long b) {
    asm("fma.rn.f32x2 %0, %1, %2, %3;" : "=l"(d) : "l"(a), "l"(b), "l"(d));
}
__device__ __forceinline__ float2 upk(unsigned long long v) {
    float2 r;
    asm("mov.b64 {%0, %1}, %2;" : "=f"(r.x), "=f"(r.y) : "l"(v));
    return r;
}
__device__ __forceinline__ float sigmoidf(float v) {
    return 1.0f / (1.0f + __expf(-v));
}
__device__ __forceinline__ void stream_bar(int id) {
    asm volatile("bar.sync %0, 64;" :: "r"(id) : "memory");
}
__device__ __forceinline__ unsigned pack_bf2(float a, float b) {
    __nv_bfloat162 t = __float22bfloat162_rn(make_float2(a, b));
    return *(unsigned*)&t;
}
__device__ __forceinline__ uint32_t smem_u32(const void* p) {
    uint32_t a;
    asm("{ .reg .u64 t; cvta.to.shared.u64 t, %1; cvt.u32.u64 %0, t; }"
        : "=r"(a) : "l"(p));
    return a;
}
__device__ __forceinline__ void cp16(uint32_t dst, const void* src) {
    asm volatile("cp.async.cg.shared.global [%0], [%1], 16;"
                 :: "r"(dst), "l"(src) : "memory");
}
#define CP_COMMIT() asm volatile("cp.async.commit_group;" ::: "memory")
#define CP_WAIT0()  asm volatile("cp.async.wait_group 0;" ::: "memory")

__device__ __forceinline__ bool mask_on(const void* mask, int mm, int t) {
    if (mm == 1) return ((const int*)mask)[t] != 0;
    if (mm == 2) return ((const float*)mask)[t] != 0.0f;
    return ((const unsigned char*)mask)[t] != 0;
}
__device__ __forceinline__ int detect_mode(const unsigned int* m, int lane) {
    bool ai = true, af = true;
#pragma unroll
    for (int k = 0; k < 8; ++k) {
        unsigned v = m[lane * 8 + k];
        ai &= (v <= 1u);
        af &= (v == 0u || v == 0x3F800000u);
    }
    unsigned bi = __ballot_sync(0xffffffffu, ai);
    unsigned bf = __ballot_sync(0xffffffffu, af);
    return (bi == 0xffffffffu) ? 1 : ((bf == 0xffffffffu) ? 2 : 0);
}

// Monotonic grid barrier (all nb blocks co-resident; counter never resets).
__device__ __forceinline__ void grid_barrier(unsigned* bar, unsigned nb) {
    __syncthreads();
    if (threadIdx.x == 0) {
        __threadfence();
        unsigned r = atomicAdd(bar, 1u);
        unsigned target = (r / nb + 1u) * nb;
        while (*((volatile unsigned*)bar) < target) {}
    }
    __syncthreads();
}

// -------------------- kernel 1: one-pass ordered per-batch compaction ------
__global__ void k_prep(const void* mask) {
    __shared__ int wcnt[8];
    __shared__ int s_mode;
    const int tid = threadIdx.x, bid = blockIdx.x;
    const int lane = tid & 31, wid = tid >> 5;

    if (bid == 0 && tid == 0) g_work = 0u;   // reset dynamic scheduler
    if (wid == 0) {
        int md = detect_mode((const unsigned int*)mask, lane);
        if (lane == 0) s_mode = md;
    }
    const int g = bid * 256 + tid;
    if (bid < 64) g_acc[g] = 0.0f;
    if (g < Bq) g_bsum[g] = 0.0f;
    __syncthreads();

    const bool on = mask_on(mask, s_mode, g);
    const unsigned bal = __ballot_sync(0xffffffffu, on);
    if (lane == 0) wcnt[wid] = __popc(bal);
    __syncthreads();

    int btot = 0, wbase = 0;
#pragma unroll
    for (int w = 0; w < 8; ++w) {
        if (w < wid) wbase += wcnt[w];
        btot += wcnt[w];
    }
    if (tid == 0) g_bcnt[bid] = btot;

    grid_barrier(&g_bar1, 256);

    const int b = bid >> 3;
    int off = 0, cnt = 0;
#pragma unroll
    for (int j = 0; j < 8; ++j) {
        int idx = b * 8 + j;
        int v = __ldcg(&g_bcnt[idx]);
        cnt += v;
        if (idx < bid) off += v;
    }
    if (tid == 0) g_cnt[b] = cnt;
    if (on)
        g_idx[b * 2048 + off + wbase + __popc(bal & ((1u << lane) - 1u))] = g;
}

// -------------------- kernel 2: persistent main + fused final --------------
// 512 threads = 8 independent 2-warp streams; 8-token slices. cp.async
// prefetch into per-stream fp32 buffer; in-place conversion to bf16 image;
// prefetch of the next slice issued as soon as the buffer is dead.
__global__ void __launch_bounds__(NT) k_main(const float* __restrict__ inp,
                                             const float* __restrict__ proj,
                                             const float* __restrict__ hid,
                                             const float* __restrict__ ev,
                                             float* __restrict__ out) {
    extern __shared__ float sm[];
    const int tid    = threadIdx.x;
    const int lane   = tid & 31;
    const int wid    = tid >> 5;
    const int stream = wid >> 1;     // 0..7
    const int hw     = wid & 1;      // warp within stream
    const int t64    = tid & 63;
    const int tg     = lane >> 3;    // token group (1 token per group)
    const int hg     = lane & 7;     // h group (4 h per lane)
    const int barid  = 1 + stream;   // named barriers 1..8
    const int row    = t64 >> 3;     // owned staging row (0..7)
    const int chunk  = t64 & 7;      // owned 64-float chunk within row

    float*         Fb = sm + SM_FB + stream * 4128;
    __nv_bfloat16* Xb = (__nv_bfloat16*)(Fb + 2048);     // byte offset 8192
    __nv_bfloat16* Pb = (__nv_bfloat16*)(sm + SM_PB);
    float*         Ws = sm + SM_WS + stream * (8 * WS_STRIDE);
    volatile int*  sW = (volatile int*)(sm + SM_SW);

    // ---- stage P as bf16: Pb[n][k] = proj[k*32+n] ----
    for (int i = tid; i < Dq * Hq; i += NT) {
        int k = i >> 5, n = i & 31;
        Pb[n * XB_STRIDE + k] = __float2bfloat16(proj[i]);
    }
    // ---- stage Ht (XOR chunk swizzle, proven layout) ----
    for (int i = tid; i < Hq * Hq; i += NT) {
        int k = i >> 5, h = i & 31;
        int c = h >> 2;
        sm[SM_HT + k * 32 + (((c ^ ((k >> 2) & 7)) << 2) | (h & 3))] =
            hid[h * Hq + k];
    }
    const float4 ev4 = ((const float4*)ev)[hg];

    // ---- slice table: inclusive prefix of per-batch 8-token slice counts --
    int* P    = (int*)(sm + SM_TBL);
    int* scnt = (int*)(sm + SM_TBL) + 33;
    if (tid < 32) {
        int c = g_cnt[tid];
        scnt[tid] = c;
        int x = (c + 7) >> 3;
#pragma unroll
        for (int o = 1; o < 32; o <<= 1) {
            int y = __shfl_up_sync(0xffffffffu, x, o);
            if (lane >= o) x += y;
        }
        P[tid + 1] = x;
        if (tid == 0) P[0] = 0;
    }
    if (t64 == 0) sW[stream] = (int)atomicAdd(&g_work, 1u);
    __syncthreads();
    const int NS = P[32];
    int s_cur = sW[stream];

    const uint32_t fb_dst = smem_u32(Fb) + (uint32_t)row * 2048u +
                            (uint32_t)chunk * 256u;

    // slice -> (batch, local slice, count)
    auto slice_info = [&](int s, int& b, int& sl, int& cnt) {
        int bb = 0;
        while (s >= P[bb + 1]) ++bb;
        b = bb; sl = s - P[bb]; cnt = scnt[bb];
    };
    // issue cp.async for own 256-byte chunk of a slice
    auto issue_stage = [&](int s) {
        int b, sl, cnt;
        slice_info(s, b, sl, cnt);
        int tok = g_idx[b * 2048 + min(sl * 8 + row, cnt - 1)];
        const char* src = (const char*)(inp + (size_t)tok * Dq) + chunk * 256;
#pragma unroll
        for (int j = 0; j < 16; ++j)
            cp16(fb_dst + j * 16u, src + j * 16);
    };

    if (s_cur < NS) issue_stage(s_cur);
    CP_COMMIT();

    const float* HtR0 = sm + SM_HT + (hg * 4 + 0) * 32;
    const float* HtR1 = HtR0 + 32;
    const float* HtR2 = HtR1 + 32;
    const float* HtR3 = HtR2 + 32;

    while (s_cur < NS) {
        int b, sl, cnt;
        slice_info(s_cur, b, sl, cnt);
        const int idx8 = g_idx[b * 2048 + min(sl * 8 + (lane & 7), cnt - 1)];

        // ---- wait own prefetch; read own fp32 chunk to registers ----
        CP_WAIT0();
        float4 buf[16];
        {
            const float* Fr = Fb + row * 512 + chunk * 64;
#pragma unroll
            for (int j = 0; j < 16; ++j) buf[j] = *(const float4*)(Fr + j * 4);
        }
        if (t64 == 0) sW[stream] = (int)atomicAdd(&g_work, 1u);
        stream_bar(barid);          // (1) all fp32 reads done; sW visible
        const int s_next = sW[stream];

        // ---- write bf16 image in place (dead fp32 rows 4-7 region) ----
        {
            char* Xr = (char*)Xb + row * 1040 + chunk * 128;
#pragma unroll
            for (int j = 0; j < 8; ++j) {
                uint4 pk;
                pk.x = pack_bf2(buf[2 * j].x, buf[2 * j].y);
                pk.y = pack_bf2(buf[2 * j].z, buf[2 * j].w);
                pk.z = pack_bf2(buf[2 * j + 1].x, buf[2 * j + 1].y);
                pk.w = pack_bf2(buf[2 * j + 1].z, buf[2 * j + 1].w);
                *(uint4*)(Xr + j * 16) = pk;
            }
        }
        stream_bar(barid);          // (2) Xb ready

        // ---- projector GEMM: warp 0 -> Z[8 tok x 32 h] (m8n32k16) ----
        if (hw == 0) {
            wmma::fragment<wmma::accumulator, 8, 32, 16, float> c;
            wmma::fill_fragment(c, 0.0f);
#pragma unroll 4
            for (int ks = 0; ks < 32; ++ks) {
                wmma::fragment<wmma::matrix_a, 8, 32, 16, __nv_bfloat16,
                               wmma::row_major> a;
                wmma::fragment<wmma::matrix_b, 8, 32, 16, __nv_bfloat16,
                               wmma::col_major> bf;
                wmma::load_matrix_sync(a, Xb + ks * 16, XB_STRIDE);
                wmma::load_matrix_sync(bf, Pb + ks * 16, XB_STRIDE);
                wmma::mma_sync(c, a, bf, c);
            }
#pragma unroll
            for (int t = 0; t < c.num_elements; ++t)
                c.x[t] = sigmoidf(c.x[t] * RSCALE);
            wmma::store_matrix_sync(Ws, c, WS_STRIDE, wmma::mem_row_major);
        }
        stream_bar(barid);          // (3) Ws ready; F buffer fully dead

        // ---- prefetch next slice (overlaps hidden/eval/epilogue) ----
        if (s_next < NS) issue_stage(s_next);
        CP_COMMIT();

        // ---- hidden layer (fp32 f32x2): 1 token per lane-group ----
        const int trow = hw * 4 + tg;
        unsigned long long acc1[4];
#pragma unroll
        for (int j = 0; j < 4; ++j) acc1[j] = 0ull;
        const float* w0r = Ws + trow * WS_STRIDE;
#pragma unroll
        for (int c = 0; c < 8; ++c) {
            const int h0 = c << 2;
            const int po = ((c ^ hg) << 2);
            ulonglong2 wa = *(const ulonglong2*)(w0r + h0);
            ulonglong2 q0 = *(const ulonglong2*)(HtR0 + po);
            ulonglong2 q1 = *(const ulonglong2*)(HtR1 + po);
            ulonglong2 q2 = *(const ulonglong2*)(HtR2 + po);
            ulonglong2 q3 = *(const ulonglong2*)(HtR3 + po);
            fma2(acc1[0], wa.x, q0.x); fma2(acc1[0], wa.y, q0.y);
            fma2(acc1[1], wa.x, q1.x); fma2(acc1[1], wa.y, q1.y);
            fma2(acc1[2], wa.x, q2.x); fma2(acc1[2], wa.y, q2.y);
            fma2(acc1[3], wa.x, q3.x); fma2(acc1[3], wa.y, q3.y);
        }

        // ---- evaluator + final sigmoid + exp; validity gates wf ----
        {
            float2 a0 = upk(acc1[0]);
            float2 a1 = upk(acc1[1]);
            float2 a2 = upk(acc1[2]);
            float2 a3 = upk(acc1[3]);
            float e = sigmoidf((a0.x + a0.y) * RSCALE) * ev4.x +
                      sigmoidf((a1.x + a1.y) * RSCALE) * ev4.y +
                      sigmoidf((a2.x + a2.y) * RSCALE) * ev4.z +
                      sigmoidf((a3.x + a3.y) * RSCALE) * ev4.w;
            e += __shfl_xor_sync(0xffffffffu, e, 1);
            e += __shfl_xor_sync(0xffffffffu, e, 2);
            e += __shfl_xor_sync(0xffffffffu, e, 4);
            float z = sigmoidf(e * RSCALE);
            bool valid = (sl * 8 + trow) < cnt;
            float wf = valid ? __expf(z) : 0.0f;
            if (hg == 0) Ws[trow * WS_STRIDE + 32] = wf;
            // warp's 4-token weight sum -> g_bsum
            float ww = (hg == 0) ? wf : 0.0f;
            ww += __shfl_xor_sync(0xffffffffu, ww, 8);
            ww += __shfl_xor_sync(0xffffffffu, ww, 16);
            if (lane == 0) atomicAdd(&g_bsum[b], ww);
        }
        stream_bar(barid);          // (4) all 8 wf visible

        // ---- epilogue: warp hw covers d-half over 8 tokens (global fp32,
        //      L2-hot), batched 4 tokens; 1 atomic per output element ----
        {
            float4 accv0 = make_float4(0.f, 0.f, 0.f, 0.f);
            float4 accv1 = make_float4(0.f, 0.f, 0.f, 0.f);
#pragma unroll
            for (int gblk = 0; gblk < 2; ++gblk) {
                float4 v0[4], v1[4];
                float wfv[4];
#pragma unroll
                for (int t = 0; t < 4; ++t) {
                    int tt = gblk * 4 + t;
                    int tok = __shfl_sync(0xffffffffu, idx8, tt);
                    const float4* xg =
                        (const float4*)(inp + (size_t)tok * Dq) + hw * 64 + lane;
                    v0[t] = __ldg(xg);
                    v1[t] = __ldg(xg + 32);
                    wfv[t] = Ws[tt * WS_STRIDE + 32];
                }
#pragma unroll
                for (int t = 0; t < 4; ++t) {
                    accv0.x += wfv[t] * v0[t].x;
                    accv0.y += wfv[t] * v0[t].y;
                    accv0.z += wfv[t] * v0[t].z;
                    accv0.w += wfv[t] * v0[t].w;
                    accv1.x += wfv[t] * v1[t].x;
                    accv1.y += wfv[t] * v1[t].y;
                    accv1.z += wfv[t] * v1[t].z;
                    accv1.w += wfv[t] * v1[t].w;
                }
            }
            float* dst = g_acc + b * Dq + hw * 256;
            int d0 = lane * 4;
            atomicAdd(dst + d0 + 0, accv0.x);
            atomicAdd(dst + d0 + 1, accv0.y);
            atomicAdd(dst + d0 + 2, accv0.z);
            atomicAdd(dst + d0 + 3, accv0.w);
            atomicAdd(dst + 128 + d0 + 0, accv1.x);
            atomicAdd(dst + 128 + d0 + 1, accv1.y);
            atomicAdd(dst + 128 + d0 + 2, accv1.z);
            atomicAdd(dst + 128 + d0 + 3, accv1.w);
        }

        s_cur = s_next;
    }

    // ---- fused final: grid barrier, then normalize ----
    grid_barrier(&g_bar2, GRID);
    const int g = blockIdx.x * NT + tid;
    if (g < Bq * Dq)
        out[g] = __ldcg(&g_acc[g]) / (__ldcg(&g_bsum[g >> 9]) + 1e-12f);
}

// -------------------- launcher --------------------
extern "C" void kernel_launch(void* const* d_in, const int* in_sizes, int n_in,
                              void* d_out, int out_size) {
    const float* inp  = (const float*)d_in[0];
    const void*  mask = d_in[1];
    const float* proj = (const float*)d_in[2];
    const float* hid  = (const float*)d_in[3];
    const float* ev   = (const float*)d_in[4];
    float* out = (float*)d_out;

    cudaFuncSetAttribute(k_main, cudaFuncAttributeMaxDynamicSharedMemorySize,
                         SMEM_BYTES);

    k_prep<<<256, 256>>>(mask);
    k_main<<<GRID, NT, SMEM_BYTES>>>(inp, proj, hid, ev, out);
}

// round 17
// speedup vs baseline: 1.8455x; 1.8455x over previous
#include <cuda_runtime.h>
#include <cuda_bf16.h>
#include <mma.h>
#include <cstdint>

using namespace nvcuda;

// Problem constants
#define Bq 32
#define Sq 2048
#define Dq 512
#define Hq 32
#define NTOK (Bq * Sq)        // 65536
#define GRID 152
#define NT   512              // 16 warps = 8 independent streams of 2

// ---------------- shared layout (float offsets) ----------------
#define XB_STRIDE 520             // bf16 row stride (1040B -> 16B bank rotation)
#define WS_STRIDE 40
#define SM_HT    0                // Ht swizzled 32x32                 -> 1024
#define SM_TBL   1024             // ints P[33]+scnt[32], padded       -> 1104
#define SM_SW    1104             // per-stream work slots (8 ints)    -> 1120
#define SM_WS    1120             // Ws[8][16][40]                     -> 6240
#define SM_X16   6240             // X bf16 [8][16][520] (33280 f)     -> 39520
#define SM_PT16  39520            // P bf16 [32][520] (8320 f)         -> 47840
#define SM_FLOATS 47840
#define SMEM_BYTES (SM_FLOATS * 4)   // 191360

#define RSCALE 0.17677669529663687f  // 1/sqrt(32)

// ---------------- scratch ----------------
__device__ int      g_bcnt[256];
__device__ int      g_cnt[Bq];
__device__ int      g_idx[NTOK];
__device__ float    g_bsum[Bq];
__device__ float    g_acc[Bq * Dq];
__device__ unsigned g_bar1 = 0u;
__device__ unsigned g_bar2 = 0u;
__device__ unsigned g_work = 0u;     // dynamic slice counter (reset by k_prep)

// ---------------- helpers ----------------
__device__ __forceinline__ void fma2(unsigned long long& d,
                                     unsigned long long a,
                                     unsigned long long b) {
    asm("fma.rn.f32x2 %0, %1, %2, %3;" : "=l"(d) : "l"(a), "l"(b), "l"(d));
}
__device__ __forceinline__ float2 upk(unsigned long long v) {
    float2 r;
    asm("mov.b64 {%0, %1}, %2;" : "=f"(r.x), "=f"(r.y) : "l"(v));
    return r;
}
__device__ __forceinline__ float sigmoidf(float v) {
    return 1.0f / (1.0f + __expf(-v));
}
__device__ __forceinline__ void stream_bar(int id) {
    asm volatile("bar.sync %0, 64;" :: "r"(id) : "memory");
}
__device__ __forceinline__ unsigned pack_bf2(float a, float b) {
    __nv_bfloat162 t = __float22bfloat162_rn(make_float2(a, b));
    return *(unsigned*)&t;
}
__device__ __forceinline__ void prefetch_l2(const void* p) {
    asm volatile("prefetch.global.L2 [%0];" :: "l"(p));
}
__device__ __forceinline__ bool mask_on(const void* mask, int mm, int t) {
    if (mm == 1) return ((const int*)mask)[t] != 0;
    if (mm == 2) return ((const float*)mask)[t] != 0.0f;
    return ((const unsigned char*)mask)[t] != 0;
}
__device__ __forceinline__ int detect_mode(const unsigned int* m, int lane) {
    bool ai = true, af = true;
#pragma unroll
    for (int k = 0; k < 8; ++k) {
        unsigned v = m[lane * 8 + k];
        ai &= (v <= 1u);
        af &= (v == 0u || v == 0x3F800000u);
    }
    unsigned bi = __ballot_sync(0xffffffffu, ai);
    unsigned bf = __ballot_sync(0xffffffffu, af);
    return (bi == 0xffffffffu) ? 1 : ((bf == 0xffffffffu) ? 2 : 0);
}

// Monotonic grid barrier (all nb blocks co-resident; counter never resets).
__device__ __forceinline__ void grid_barrier(unsigned* bar, unsigned nb) {
    __syncthreads();
    if (threadIdx.x == 0) {
        __threadfence();
        unsigned r = atomicAdd(bar, 1u);
        unsigned target = (r / nb + 1u) * nb;
        while (*((volatile unsigned*)bar) < target) {}
    }
    __syncthreads();
}

// -------------------- kernel 1: one-pass ordered per-batch compaction ------
__global__ void k_prep(const void* mask) {
    __shared__ int wcnt[8];
    __shared__ int s_mode;
    const int tid = threadIdx.x, bid = blockIdx.x;
    const int lane = tid & 31, wid = tid >> 5;

    if (bid == 0 && tid == 0) g_work = 0u;   // reset dynamic scheduler
    if (wid == 0) {
        int md = detect_mode((const unsigned int*)mask, lane);
        if (lane == 0) s_mode = md;
    }
    const int g = bid * 256 + tid;
    if (bid < 64) g_acc[g] = 0.0f;
    if (g < Bq) g_bsum[g] = 0.0f;
    __syncthreads();

    const bool on = mask_on(mask, s_mode, g);
    const unsigned bal = __ballot_sync(0xffffffffu, on);
    if (lane == 0) wcnt[wid] = __popc(bal);
    __syncthreads();

    int btot = 0, wbase = 0;
#pragma unroll
    for (int w = 0; w < 8; ++w) {
        if (w < wid) wbase += wcnt[w];
        btot += wcnt[w];
    }
    if (tid == 0) g_bcnt[bid] = btot;

    grid_barrier(&g_bar1, 256);

    const int b = bid >> 3;
    int off = 0, cnt = 0;
#pragma unroll
    for (int j = 0; j < 8; ++j) {
        int idx = b * 8 + j;
        int v = __ldcg(&g_bcnt[idx]);
        cnt += v;
        if (idx < bid) off += v;
    }
    if (tid == 0) g_cnt[b] = cnt;
    if (on)
        g_idx[b * 2048 + off + wbase + __popc(bal & ((1u << lane) - 1u))] = g;
}

// -------------------- kernel 2: persistent main + fused final --------------
// 512 threads = 8 independent 2-warp streams; 16-token slices. R14 structure
// plus next-slice index load + L2 prefetch hidden under the epilogue.
__global__ void __launch_bounds__(NT) k_main(const float* __restrict__ inp,
                                             const float* __restrict__ proj,
                                             const float* __restrict__ hid,
                                             const float* __restrict__ ev,
                                             float* __restrict__ out) {
    extern __shared__ float sm[];
    const int tid    = threadIdx.x;
    const int lane   = tid & 31;
    const int wid    = tid >> 5;
    const int stream = wid >> 1;     // 0..7
    const int hw     = wid & 1;      // warp within stream (= wmma ni)
    const int t64    = tid & 63;
    const int tg     = lane >> 3;
    const int hg     = lane & 7;
    const int barid  = 1 + stream;   // named barriers 1..8

    __nv_bfloat16* Xb = (__nv_bfloat16*)(sm + SM_X16) + stream * (16 * XB_STRIDE);
    __nv_bfloat16* Pb = (__nv_bfloat16*)(sm + SM_PT16);
    float* Ws = sm + SM_WS + stream * (16 * WS_STRIDE);
    volatile int* sW = (volatile int*)(sm + SM_SW);

    // ---- stage P as bf16: Pb[n][k] = proj[k*32+n] ----
    for (int i = tid; i < Dq * Hq; i += NT) {
        int k = i >> 5, n = i & 31;
        Pb[n * XB_STRIDE + k] = __float2bfloat16(proj[i]);
    }
    // ---- stage Ht (XOR chunk swizzle, proven layout) ----
    for (int i = tid; i < Hq * Hq; i += NT) {
        int k = i >> 5, h = i & 31;
        int c = h >> 2;
        sm[SM_HT + k * 32 + (((c ^ ((k >> 2) & 7)) << 2) | (h & 3))] =
            hid[h * Hq + k];
    }
    const float4 ev4 = ((const float4*)ev)[hg];

    // ---- slice table: inclusive prefix of per-batch 16-token slice counts --
    int* P    = (int*)(sm + SM_TBL);
    int* scnt = (int*)(sm + SM_TBL) + 33;
    if (tid < 32) {
        int c = g_cnt[tid];
        scnt[tid] = c;
        int x = (c + 15) >> 4;
#pragma unroll
        for (int o = 1; o < 32; o <<= 1) {
            int y = __shfl_up_sync(0xffffffffu, x, o);
            if (lane >= o) x += y;
        }
        P[tid + 1] = x;
        if (tid == 0) P[0] = 0;
    }
    if (t64 == 0) sW[stream] = (int)atomicAdd(&g_work, 1u);
    __syncthreads();
    const int NS = P[32];

    float* Wwarp = Ws + hw * (8 * WS_STRIDE);   // own 8 token rows

    const float* HtR0 = sm + SM_HT + (hg * 4 + 0) * 32;
    const float* HtR1 = HtR0 + 32;
    const float* HtR2 = HtR1 + 32;
    const float* HtR3 = HtR2 + 32;

    // slice -> (batch, local slice, count)
    auto slice_info = [&](int s, int& b, int& sl, int& cnt) {
        int bb = 0;
        while (s >= P[bb + 1]) ++bb;
        b = bb; sl = s - P[bb]; cnt = scnt[bb];
    };

    // ---- loop-carried state for the current slice ----
    int s_cur = sW[stream];
    int b, sl, cnt, myidx, idx16;
    if (s_cur < NS) {
        slice_info(s_cur, b, sl, cnt);
        myidx = g_idx[b * 2048 + min(sl * 16 + hw * 8 + (lane & 7), cnt - 1)];
        idx16 = g_idx[b * 2048 + min(sl * 16 + (lane & 15), cnt - 1)];
    }

    while (s_cur < NS) {
        // ---- stage own 8 token rows as bf16, 4 rows per register batch ----
#pragma unroll
        for (int half = 0; half < 2; ++half) {
            float4 buf[4][4];
#pragma unroll
            for (int t = 0; t < 4; ++t) {
                int tok = __shfl_sync(0xffffffffu, myidx, half * 4 + t);
                const float4* src =
                    (const float4*)(inp + (size_t)tok * Dq) + lane * 4;
                buf[t][0] = src[0];
                buf[t][1] = src[1];
                buf[t][2] = src[2];
                buf[t][3] = src[3];
            }
#pragma unroll
            for (int t = 0; t < 4; ++t) {
                uint4 pkA, pkB;
                pkA.x = pack_bf2(buf[t][0].x, buf[t][0].y);
                pkA.y = pack_bf2(buf[t][0].z, buf[t][0].w);
                pkA.z = pack_bf2(buf[t][1].x, buf[t][1].y);
                pkA.w = pack_bf2(buf[t][1].z, buf[t][1].w);
                pkB.x = pack_bf2(buf[t][2].x, buf[t][2].y);
                pkB.y = pack_bf2(buf[t][2].z, buf[t][2].w);
                pkB.z = pack_bf2(buf[t][3].x, buf[t][3].y);
                pkB.w = pack_bf2(buf[t][3].z, buf[t][3].w);
                uint4* dst = (uint4*)(Xb + (hw * 8 + half * 4 + t) * XB_STRIDE +
                                      lane * 16);
                dst[0] = pkA;
                dst[1] = pkB;
            }
        }
        stream_bar(barid);              // X ready (both warps)

        // ---- projector GEMM: warp hw -> Z tile [16 tok x 16 h] ----
        {
            wmma::fragment<wmma::accumulator, 16, 16, 16, float> c;
            wmma::fill_fragment(c, 0.0f);
            const __nv_bfloat16* Bbase = Pb + hw * 16 * XB_STRIDE;
#pragma unroll 4
            for (int ks = 0; ks < 32; ++ks) {
                wmma::fragment<wmma::matrix_a, 16, 16, 16, __nv_bfloat16,
                               wmma::row_major> a;
                wmma::fragment<wmma::matrix_b, 16, 16, 16, __nv_bfloat16,
                               wmma::col_major> bf;
                wmma::load_matrix_sync(a, Xb + ks * 16, XB_STRIDE);
                wmma::load_matrix_sync(bf, Bbase + ks * 16, XB_STRIDE);
                wmma::mma_sync(c, a, bf, c);
            }
#pragma unroll
            for (int t = 0; t < c.num_elements; ++t)
                c.x[t] = sigmoidf(c.x[t] * RSCALE);
            wmma::store_matrix_sync(Ws + hw * 16, c, WS_STRIDE,
                                    wmma::mem_row_major);
        }
        stream_bar(barid);              // full Ws (both ni halves) ready

        // ---- hidden layer (fp32 f32x2, proven loop): warp's 8 tokens ----
        unsigned long long acc1[2][4];
#pragma unroll
        for (int a = 0; a < 2; ++a)
#pragma unroll
            for (int b2 = 0; b2 < 4; ++b2) acc1[a][b2] = 0ull;

        const float* w0a = Wwarp + 2 * tg * WS_STRIDE;
        const float* w0b = w0a + WS_STRIDE;
#pragma unroll
        for (int c = 0; c < 8; ++c) {
            const int h0 = c << 2;
            const int po = ((c ^ hg) << 2);
            ulonglong2 wa = *(const ulonglong2*)(w0a + h0);
            ulonglong2 wb = *(const ulonglong2*)(w0b + h0);
            ulonglong2 q0 = *(const ulonglong2*)(HtR0 + po);
            ulonglong2 q1 = *(const ulonglong2*)(HtR1 + po);
            ulonglong2 q2 = *(const ulonglong2*)(HtR2 + po);
            ulonglong2 q3 = *(const ulonglong2*)(HtR3 + po);
            fma2(acc1[0][0], wa.x, q0.x); fma2(acc1[0][0], wa.y, q0.y);
            fma2(acc1[0][1], wa.x, q1.x); fma2(acc1[0][1], wa.y, q1.y);
            fma2(acc1[0][2], wa.x, q2.x); fma2(acc1[0][2], wa.y, q2.y);
            fma2(acc1[0][3], wa.x, q3.x); fma2(acc1[0][3], wa.y, q3.y);
            fma2(acc1[1][0], wb.x, q0.x); fma2(acc1[1][0], wb.y, q0.y);
            fma2(acc1[1][1], wb.x, q1.x); fma2(acc1[1][1], wb.y, q1.y);
            fma2(acc1[1][2], wb.x, q2.x); fma2(acc1[1][2], wb.y, q2.y);
            fma2(acc1[1][3], wb.x, q3.x); fma2(acc1[1][3], wb.y, q3.y);
        }

        // ---- evaluator + final sigmoid + exp; validity gates wf ----
#pragma unroll
        for (int tp = 0; tp < 2; ++tp) {
            float2 a0 = upk(acc1[tp][0]);
            float2 a1 = upk(acc1[tp][1]);
            float2 a2 = upk(acc1[tp][2]);
            float2 a3 = upk(acc1[tp][3]);
            float e = sigmoidf((a0.x + a0.y) * RSCALE) * ev4.x +
                      sigmoidf((a1.x + a1.y) * RSCALE) * ev4.y +
                      sigmoidf((a2.x + a2.y) * RSCALE) * ev4.z +
                      sigmoidf((a3.x + a3.y) * RSCALE) * ev4.w;
            e += __shfl_xor_sync(0xffffffffu, e, 1);
            e += __shfl_xor_sync(0xffffffffu, e, 2);
            e += __shfl_xor_sync(0xffffffffu, e, 4);
            float z = sigmoidf(e * RSCALE);
            const int trow = 2 * tg + tp;
            bool valid = (sl * 16 + hw * 8 + trow) < cnt;
            if (hg == 0)
                Wwarp[trow * WS_STRIDE + 32] = valid ? __expf(z) : 0.0f;
        }
        __syncwarp();

        // ---- own-8 weight sum -> g_bsum ----
        {
            float wf8 = (lane < 8) ? Wwarp[lane * WS_STRIDE + 32] : 0.0f;
#pragma unroll
            for (int o = 4; o; o >>= 1)
                wf8 += __shfl_xor_sync(0xffffffffu, wf8, o);
            if (lane == 0) atomicAdd(&g_bsum[b], wf8);
        }

        // ---- early grab of next slice ----
        if (t64 == 0) sW[stream] = (int)atomicAdd(&g_work, 1u);
        stream_bar(barid);              // all 16 wf visible; sW written

        // ---- next-slice index load + L2 prefetch (hidden under epilogue) ---
        const int s_next = sW[stream];
        int nb = 0, nsl = 0, ncnt = 0, n_myidx = 0, n_idx16 = 0;
        if (s_next < NS) {
            slice_info(s_next, nb, nsl, ncnt);
            n_myidx = g_idx[nb * 2048 +
                            min(nsl * 16 + hw * 8 + (lane & 7), ncnt - 1)];
            n_idx16 = g_idx[nb * 2048 +
                            min(nsl * 16 + (lane & 15), ncnt - 1)];
            // prefetch all 128 cache lines of own 8 next rows (4 lines/lane)
#pragma unroll
            for (int j = 0; j < 4; ++j) {
                int li  = lane * 4 + j;            // 0..127
                int r   = li >> 4;                 // row 0..7
                int off = (li & 15) * 128;         // byte offset within row
                int tok = __shfl_sync(0xffffffffu, n_myidx, r);
                prefetch_l2((const char*)(inp + (size_t)tok * Dq) + off);
            }
        }

        // ---- epilogue: warp hw covers d-half over all 16 tokens, batched
        //      4 tokens per register group; 1 atomic per output element ----
        {
            float4 accv0 = make_float4(0.f, 0.f, 0.f, 0.f);
            float4 accv1 = make_float4(0.f, 0.f, 0.f, 0.f);
#pragma unroll
            for (int gblk = 0; gblk < 4; ++gblk) {
                float4 v0[4], v1[4];
                float wfv[4];
#pragma unroll
                for (int t = 0; t < 4; ++t) {
                    int tt = gblk * 4 + t;
                    int tok = __shfl_sync(0xffffffffu, idx16, tt);
                    const float4* xg =
                        (const float4*)(inp + (size_t)tok * Dq) + hw * 64 + lane;
                    v0[t] = __ldg(xg);
                    v1[t] = __ldg(xg + 32);
                    wfv[t] = Ws[tt * WS_STRIDE + 32];
                }
#pragma unroll
                for (int t = 0; t < 4; ++t) {
                    accv0.x += wfv[t] * v0[t].x;
                    accv0.y += wfv[t] * v0[t].y;
                    accv0.z += wfv[t] * v0[t].z;
                    accv0.w += wfv[t] * v0[t].w;
                    accv1.x += wfv[t] * v1[t].x;
                    accv1.y += wfv[t] * v1[t].y;
                    accv1.z += wfv[t] * v1[t].z;
                    accv1.w += wfv[t] * v1[t].w;
                }
            }
            float* dst = g_acc + b * Dq + hw * 256;
            int d0 = lane * 4;
            atomicAdd(dst + d0 + 0, accv0.x);
            atomicAdd(dst + d0 + 1, accv0.y);
            atomicAdd(dst + d0 + 2, accv0.z);
            atomicAdd(dst + d0 + 3, accv0.w);
            atomicAdd(dst + 128 + d0 + 0, accv1.x);
            atomicAdd(dst + 128 + d0 + 1, accv1.y);
            atomicAdd(dst + 128 + d0 + 2, accv1.z);
            atomicAdd(dst + 128 + d0 + 3, accv1.w);
        }
        stream_bar(barid);              // epilogue done before next overwrite

        s_cur = s_next;
        b = nb; sl = nsl; cnt = ncnt;
        myidx = n_myidx; idx16 = n_idx16;
    }

    // ---- fused final: grid barrier, then normalize ----
    grid_barrier(&g_bar2, GRID);
    const int g = blockIdx.x * NT + tid;
    if (g < Bq * Dq)
        out[g] = __ldcg(&g_acc[g]) / (__ldcg(&g_bsum[g >> 9]) + 1e-12f);
}

// -------------------- launcher --------------------
extern "C" void kernel_launch(void* const* d_in, const int* in_sizes, int n_in,
                              void* d_out, int out_size) {
    const float* inp  = (const float*)d_in[0];
    const void*  mask = d_in[1];
    const float* proj = (const float*)d_in[2];
    const float* hid  = (const float*)d_in[3];
    const float* ev   = (const float*)d_in[4];
    float* out = (float*)d_out;

    cudaFuncSetAttribute(k_main, cudaFuncAttributeMaxDynamicSharedMemorySize,
                         SMEM_BYTES);

    k_prep<<<256, 256>>>(mask);
    k_main<<<GRID, NT, SMEM_BYTES>>>(inp, proj, hid, ev, out);
}